// round 2
// baseline (speedup 1.0000x reference)
#include <cuda_runtime.h>
#include <cuda_bf16.h>

#define DIM        128
#define MAX_ENT    50048
#define MAX_REL    24
#define MAX_NEEDED 4096

// ---------------- device scratch (static; no allocations) ----------------
__device__ int   g_is64;                                           // 1 if idx arrays are int64
__device__ int   g_slot[MAX_ENT];                                  // node -> slot or -1/-2
__device__ int   g_needed_nodes[MAX_NEEDED];
__device__ int   g_n_needed;
__device__ float g_msg[(size_t)MAX_NEEDED * MAX_REL * DIM];
__device__ float g_cnt[MAX_NEEDED * MAX_REL];
__device__ float g_agg[MAX_NEEDED * DIM];

// Load an index element from a buffer of unknown (int32 vs int64) dtype.
__device__ __forceinline__ int ld_idx(const void* p, size_t i, int is64) {
    if (is64) return (int)((const long long*)p)[i];
    return ((const int*)p)[i];
}

// ---------------- kernels ----------------

// Detect int64 vs int32: for non-negative little-endian int64, the high word
// of every element is 0. For random int32 node ids, odd words are node ids
// (zero with prob 1/50000 each) -> 256 all-zero is impossible in practice.
__global__ void k_detect(const unsigned int* __restrict__ ei_words) {
    __shared__ int any_nonzero;
    if (threadIdx.x == 0) any_nonzero = 0;
    __syncthreads();
    unsigned int w = ei_words[threadIdx.x * 2 + 1];   // high word if int64
    if (w != 0u) atomicOr(&any_nonzero, 1);
    __syncthreads();
    if (threadIdx.x == 0) g_is64 = any_nonzero ? 0 : 1;
}

__global__ void k_reset(int n_ent) {
    int i = blockIdx.x * blockDim.x + threadIdx.x;
    if (i < n_ent) g_slot[i] = -1;
    if (i == 0) g_n_needed = 0;
}

__global__ void k_mark(const void* __restrict__ sample, int batch) {
    int is64 = g_is64;
    int i = blockIdx.x * blockDim.x + threadIdx.x;
    if (i >= batch * 2) return;
    int b = i >> 1;
    int c = (i & 1) * 2;               // columns 0 and 2 (head/tail)
    int node = ld_idx(sample, (size_t)b * 3 + c, is64);
    atomicCAS(&g_slot[node], -1, -2);
}

__global__ void k_compact(int n_ent) {
    int i = blockIdx.x * blockDim.x + threadIdx.x;
    if (i >= n_ent) return;
    if (g_slot[i] == -2) {
        int s = atomicAdd(&g_n_needed, 1);
        g_slot[i] = s;
        g_needed_nodes[s] = i;
    }
}

__global__ void k_zero(int n_rel) {
    int nn = g_n_needed;
    int stride = gridDim.x * blockDim.x;
    int tid = blockIdx.x * blockDim.x + threadIdx.x;
    int n_msg = nn * n_rel * DIM;
    for (int i = tid; i < n_msg; i += stride) g_msg[i] = 0.0f;
    int n_cnt = nn * n_rel;
    for (int i = tid; i < n_cnt; i += stride) g_cnt[i] = 0.0f;
    int n_agg = nn * DIM;
    for (int i = tid; i < n_agg; i += stride) g_agg[i] = 0.0f;
}

__global__ void k_scan(const void* __restrict__ edge_index,
                       const void* __restrict__ edge_type,
                       const float* __restrict__ x,
                       int n_edge, int n_rel) {
    int is64 = g_is64;
    int e = blockIdx.x * blockDim.x + threadIdx.x;
    if (e >= n_edge) return;
    int dst = ld_idx(edge_index, (size_t)n_edge + e, is64);
    int s = g_slot[dst];
    if (s < 0) return;
    int r   = ld_idx(edge_type, e, is64);
    int src = ld_idx(edge_index, e, is64);
    atomicAdd(&g_cnt[s * n_rel + r], 1.0f);
    const float4* xs = (const float4*)(x + (size_t)src * DIM);
    float* m = &g_msg[((size_t)s * n_rel + r) * DIM];
#pragma unroll
    for (int k = 0; k < DIM / 4; k++) {
        float4 v = xs[k];
        atomicAdd(&m[4 * k + 0], v.x);
        atomicAdd(&m[4 * k + 1], v.y);
        atomicAdd(&m[4 * k + 2], v.z);
        atomicAdd(&m[4 * k + 3], v.w);
    }
}

// grid = (n_rel + 1) * GROUPS blocks of 128 threads.
// r in [0, n_rel): msg_mean[slot][r] @ W_rel[r];  r == n_rel: x[node] @ W_root.
#define GROUPS 8
__global__ void k_gemm(const float* __restrict__ W_rel,
                       const float* __restrict__ W_root,
                       const float* __restrict__ x,
                       int n_rel) {
    __shared__ float Ws[64 * DIM];   // Ws[d * 64 + c]
    __shared__ float ms[DIM];

    int r  = blockIdx.x % (n_rel + 1);
    int sg = blockIdx.x / (n_rel + 1);
    const float* W = (r < n_rel) ? (W_rel + (size_t)r * DIM * DIM) : W_root;
    int tid = threadIdx.x;           // 128 threads
    int nn = g_n_needed;

    for (int half = 0; half < 2; half++) {
        int fbase = half * 64;
        for (int i = tid; i < 64 * DIM; i += 128) {
            int d = i >> 6, c = i & 63;
            Ws[i] = W[d * DIM + fbase + c];
        }
        __syncthreads();

        int c  = tid & 63;
        int dh = (tid >> 6) * 64;    // each column handled by 2 threads (d halves)

        for (int s = sg; s < nn; s += GROUPS) {
            bool skip = false;
            float scale = 1.0f;
            if (r < n_rel) {
                float cnt = g_cnt[s * n_rel + r];     // uniform across block
                if (cnt == 0.0f) skip = true;         // sum == 0 -> contribution 0
                else scale = 1.0f / cnt;              // max(cnt,1) == cnt for cnt>=1
            }
            if (!skip) {
                if (r < n_rel)
                    ms[tid] = g_msg[((size_t)s * n_rel + r) * DIM + tid] * scale;
                else
                    ms[tid] = x[(size_t)g_needed_nodes[s] * DIM + tid];
            }
            __syncthreads();
            if (!skip) {
                float acc = 0.0f;
#pragma unroll
                for (int k = 0; k < 16; k++) {
                    int d = dh + k * 4;
                    float4 mv = *(const float4*)&ms[d];
                    acc += mv.x * Ws[(d + 0) * 64 + c];
                    acc += mv.y * Ws[(d + 1) * 64 + c];
                    acc += mv.z * Ws[(d + 2) * 64 + c];
                    acc += mv.w * Ws[(d + 3) * 64 + c];
                }
                atomicAdd(&g_agg[s * DIM + fbase + c], acc);
            }
            __syncthreads();
        }
        __syncthreads();
    }
}

__global__ void k_out(const void* __restrict__ sample,
                      const float* __restrict__ init_rel,
                      float* __restrict__ out,
                      int batch) {
    int is64 = g_is64;
    int i = blockIdx.x * blockDim.x + threadIdx.x;
    if (i >= batch * DIM) return;
    int b = i >> 7;
    int d = i & (DIM - 1);
    int h   = ld_idx(sample, (size_t)b * 3 + 0, is64);
    int rel = ld_idx(sample, (size_t)b * 3 + 1, is64);
    int t   = ld_idx(sample, (size_t)b * 3 + 2, is64);
    int sh = g_slot[h];
    int st = g_slot[t];
    float hv = tanhf(g_agg[sh * DIM + d]);
    float tv = tanhf(g_agg[st * DIM + d]);
    out[i] = hv * (init_rel[rel * DIM + d] * tv);
}

// ---------------- launch ----------------
extern "C" void kernel_launch(void* const* d_in, const int* in_sizes, int n_in,
                              void* d_out, int out_size) {
    const float* init_embed = (const float*)d_in[0];
    const float* init_rel   = (const float*)d_in[1];
    const float* W_rel      = (const float*)d_in[2];
    const float* W_root     = (const float*)d_in[3];
    const void*  edge_index = d_in[4];
    const void*  edge_type  = d_in[5];
    const void*  sample     = d_in[6];
    float* out = (float*)d_out;

    int n_ent  = in_sizes[0] / DIM;
    int n_rel  = in_sizes[1] / DIM;
    int n_edge = in_sizes[5];
    int batch  = in_sizes[6] / 3;

    k_detect <<<1, 256>>>((const unsigned int*)edge_index);
    k_reset  <<<(n_ent + 255) / 256, 256>>>(n_ent);
    k_mark   <<<(batch * 2 + 255) / 256, 256>>>(sample, batch);
    k_compact<<<(n_ent + 255) / 256, 256>>>(n_ent);
    k_zero   <<<256, 256>>>(n_rel);
    k_scan   <<<(n_edge + 255) / 256, 256>>>(edge_index, edge_type, init_embed,
                                             n_edge, n_rel);
    k_gemm   <<<(n_rel + 1) * GROUPS, 128>>>(W_rel, W_root, init_embed, n_rel);
    k_out    <<<(batch * DIM + 255) / 256, 256>>>(sample, init_rel, out, batch);
}

// round 3
// speedup vs baseline: 1.0667x; 1.0667x over previous
#include <cuda_runtime.h>
#include <cuda_bf16.h>

#define DIM        128
#define MAX_ENT    50048
#define MAX_REL    24
#define MAX_NEEDED 4096
#define GROUPS     8

// ---------------- device scratch (static zero-init == "clean" state) ------
// g_slot[node]: 0 = free, 1 = being claimed, s+2 = assigned slot s
__device__ int   g_is64;
__device__ int   g_slot[MAX_ENT];
__device__ int   g_needed_nodes[MAX_NEEDED];
__device__ int   g_n_needed;
__device__ int   g_nn_copy;
__device__ float g_msg[(size_t)MAX_NEEDED * MAX_REL * DIM];
__device__ float g_cnt[MAX_NEEDED * MAX_REL];
__device__ float g_agg[MAX_NEEDED * DIM];

__device__ __forceinline__ int ld_idx(const void* p, size_t i, int is64) {
    if (is64) return (int)((const long long*)p)[i];
    return ((const int*)p)[i];
}

// ---------------- 1) fused dtype-detect + mark + compact -------------------
// grid: ceil(batch*2 / 256) blocks (16 for batch=2048)
__global__ void k_mark(const unsigned int* __restrict__ ei_words,
                       const void* __restrict__ sample, int batch) {
    // Block-local dtype detect: for non-negative little-endian int64 every
    // high word of edge_index is 0; for int32 these words are node ids.
    __shared__ int s_any;
    if (threadIdx.x == 0) s_any = 0;
    __syncthreads();
    if (ei_words[threadIdx.x * 2 + 1] != 0u) atomicOr(&s_any, 1);
    __syncthreads();
    int is64 = s_any ? 0 : 1;
    if (blockIdx.x == 0 && threadIdx.x == 0) g_is64 = is64;

    int i = blockIdx.x * blockDim.x + threadIdx.x;
    if (i >= batch * 2) return;
    int b = i >> 1;
    int c = (i & 1) * 2;                       // sample columns 0 and 2
    int node = ld_idx(sample, (size_t)b * 3 + c, is64);
    int old = atomicCAS(&g_slot[node], 0, 1);
    if (old == 0) {                            // unique claimer assigns slot
        int s = atomicAdd(&g_n_needed, 1);
        g_needed_nodes[s] = node;
        g_slot[node] = s + 2;                  // publish (visible next kernel)
    }
}

// ---------------- 2) edge scan: accumulate only needed dsts ----------------
__global__ void k_scan(const void* __restrict__ edge_index,
                       const void* __restrict__ edge_type,
                       const float* __restrict__ x,
                       int n_edge, int n_rel) {
    int is64 = g_is64;
    int e = blockIdx.x * blockDim.x + threadIdx.x;
    if (e >= n_edge) return;
    int dst = ld_idx(edge_index, (size_t)n_edge + e, is64);
    int s = g_slot[dst] - 2;
    if (s < 0) return;
    int r   = ld_idx(edge_type, e, is64);
    int src = ld_idx(edge_index, e, is64);
    atomicAdd(&g_cnt[s * n_rel + r], 1.0f);
    const float4* xs = (const float4*)(x + (size_t)src * DIM);
    float* m = &g_msg[((size_t)s * n_rel + r) * DIM];
#pragma unroll
    for (int k = 0; k < DIM / 4; k++) {
        float4 v = xs[k];
        atomicAdd(&m[4 * k + 0], v.x);
        atomicAdd(&m[4 * k + 1], v.y);
        atomicAdd(&m[4 * k + 2], v.z);
        atomicAdd(&m[4 * k + 3], v.w);
    }
}

// ---------------- 3) per-(rel, slot-group) GEMM -----------------------------
// grid = (n_rel + 1) * GROUPS blocks of 128 threads.
// r < n_rel: msg_mean[slot][r] @ W_rel[r];  r == n_rel: x[node] @ W_root.
__global__ void k_gemm(const float* __restrict__ W_rel,
                       const float* __restrict__ W_root,
                       const float* __restrict__ x,
                       int n_rel) {
    __shared__ float Ws[64 * DIM];   // Ws[d * 64 + c]
    __shared__ float ms[DIM];

    int r  = blockIdx.x % (n_rel + 1);
    int sg = blockIdx.x / (n_rel + 1);
    const float* W = (r < n_rel) ? (W_rel + (size_t)r * DIM * DIM) : W_root;
    int tid = threadIdx.x;           // 128 threads
    int nn = g_n_needed;
    if (blockIdx.x == 0 && tid == 0) g_nn_copy = nn;   // snapshot for cleanup

    for (int half = 0; half < 2; half++) {
        int fbase = half * 64;
        for (int i = tid; i < 64 * DIM; i += 128) {
            int d = i >> 6, c = i & 63;
            Ws[i] = W[d * DIM + fbase + c];
        }
        __syncthreads();

        int c  = tid & 63;
        int dh = (tid >> 6) * 64;

        for (int s = sg; s < nn; s += GROUPS) {
            bool skip = false;
            float scale = 1.0f;
            if (r < n_rel) {
                float cnt = g_cnt[s * n_rel + r];   // uniform across block
                if (cnt == 0.0f) skip = true;       // zero sum -> zero contrib
                else scale = 1.0f / cnt;            // max(cnt,1)==cnt for >=1
            }
            if (!skip) {
                if (r < n_rel)
                    ms[tid] = g_msg[((size_t)s * n_rel + r) * DIM + tid] * scale;
                else
                    ms[tid] = x[(size_t)g_needed_nodes[s] * DIM + tid];
            }
            __syncthreads();
            if (!skip) {
                float acc = 0.0f;
#pragma unroll
                for (int k = 0; k < 16; k++) {
                    int d = dh + k * 4;
                    float4 mv = *(const float4*)&ms[d];
                    acc += mv.x * Ws[(d + 0) * 64 + c];
                    acc += mv.y * Ws[(d + 1) * 64 + c];
                    acc += mv.z * Ws[(d + 2) * 64 + c];
                    acc += mv.w * Ws[(d + 3) * 64 + c];
                }
                atomicAdd(&g_agg[s * DIM + fbase + c], acc);
            }
            __syncthreads();
        }
        __syncthreads();
    }
}

// ---------------- 4) fused gather + tanh epilogue ---------------------------
__global__ void k_out(const void* __restrict__ sample,
                      const float* __restrict__ init_rel,
                      float* __restrict__ out,
                      int batch) {
    int is64 = g_is64;
    int i = blockIdx.x * blockDim.x + threadIdx.x;
    if (i >= batch * DIM) return;
    int b = i >> 7;
    int d = i & (DIM - 1);
    int h   = ld_idx(sample, (size_t)b * 3 + 0, is64);
    int rel = ld_idx(sample, (size_t)b * 3 + 1, is64);
    int t   = ld_idx(sample, (size_t)b * 3 + 2, is64);
    int sh = g_slot[h] - 2;
    int st = g_slot[t] - 2;
    float hv = tanhf(g_agg[sh * DIM + d]);
    float tv = tanhf(g_agg[st * DIM + d]);
    out[i] = hv * (init_rel[rel * DIM + d] * tv);
}

// ---------------- 5) self-clean: restore all-zero invariant ----------------
__global__ void k_cleanup(int n_rel) {
    int nn = g_nn_copy;                     // snapshot (stable during kernel)
    int tid = blockIdx.x * blockDim.x + threadIdx.x;
    int stride = gridDim.x * blockDim.x;
    size_t n_msg = (size_t)nn * n_rel * DIM;
    for (size_t i = tid; i < n_msg; i += stride) g_msg[i] = 0.0f;
    for (int i = tid; i < nn * n_rel; i += stride) g_cnt[i] = 0.0f;
    for (int i = tid; i < nn * DIM; i += stride) g_agg[i] = 0.0f;
    for (int i = tid; i < nn; i += stride) g_slot[g_needed_nodes[i]] = 0;
    if (tid == 0) g_n_needed = 0;
}

// ---------------- launch ----------------
extern "C" void kernel_launch(void* const* d_in, const int* in_sizes, int n_in,
                              void* d_out, int out_size) {
    const float* init_embed = (const float*)d_in[0];
    const float* init_rel   = (const float*)d_in[1];
    const float* W_rel      = (const float*)d_in[2];
    const float* W_root     = (const float*)d_in[3];
    const void*  edge_index = d_in[4];
    const void*  edge_type  = d_in[5];
    const void*  sample     = d_in[6];
    float* out = (float*)d_out;

    int n_rel  = in_sizes[1] / DIM;
    int n_edge = in_sizes[5];
    int batch  = in_sizes[6] / 3;

    k_mark   <<<(batch * 2 + 255) / 256, 256>>>((const unsigned int*)edge_index,
                                                sample, batch);
    k_scan   <<<(n_edge + 255) / 256, 256>>>(edge_index, edge_type, init_embed,
                                             n_edge, n_rel);
    k_gemm   <<<(n_rel + 1) * GROUPS, 128>>>(W_rel, W_root, init_embed, n_rel);
    k_out    <<<(batch * DIM + 255) / 256, 256>>>(sample, init_rel, out, batch);
    k_cleanup<<<64, 256>>>(n_rel);
}

// round 4
// speedup vs baseline: 1.2279x; 1.1511x over previous
#include <cuda_runtime.h>
#include <cuda_bf16.h>

#define DIM        128
#define MAX_ENT    50048
#define MAX_REL    24
#define MAX_NEEDED 4096
#define GROUPS     4

// ---------------- device scratch (static zero-init == "clean" state) ------
// g_slot[node]: 0 = free, 1 = being claimed, s+2 = assigned slot s
__device__ int   g_is64;
__device__ int   g_slot[MAX_ENT];
__device__ int   g_needed_nodes[MAX_NEEDED];
__device__ int   g_n_needed;
__device__ int   g_nn_copy;
__device__ float g_msg[(size_t)MAX_NEEDED * MAX_REL * DIM];
__device__ float g_cnt[MAX_NEEDED * MAX_REL];
__device__ float g_agg[MAX_NEEDED * DIM];

__device__ __forceinline__ int ld_idx(const void* p, size_t i, int is64) {
    if (is64) return (int)((const long long*)p)[i];
    return ((const int*)p)[i];
}

// fast tanh: 1 - 2/(e^{2x}+1); MUFU.EX2 + MUFU.RCP, rel err ~1e-7
__device__ __forceinline__ float ftanh(float x) {
    float e = __expf(2.0f * x);
    return 1.0f - 2.0f / (e + 1.0f);
}

// ---------------- 1) fused dtype-detect + mark + compact -------------------
__global__ void k_mark(const unsigned int* __restrict__ ei_words,
                       const void* __restrict__ sample, int batch) {
    __shared__ int s_any;
    if (threadIdx.x == 0) s_any = 0;
    __syncthreads();
    if (ei_words[threadIdx.x * 2 + 1] != 0u) atomicOr(&s_any, 1);
    __syncthreads();
    int is64 = s_any ? 0 : 1;
    if (blockIdx.x == 0 && threadIdx.x == 0) g_is64 = is64;

    int i = blockIdx.x * blockDim.x + threadIdx.x;
    if (i >= batch * 2) return;
    int b = i >> 1;
    int c = (i & 1) * 2;                       // sample columns 0 and 2
    int node = ld_idx(sample, (size_t)b * 3 + c, is64);
    int old = atomicCAS(&g_slot[node], 0, 1);
    if (old == 0) {                            // unique claimer assigns slot
        int s = atomicAdd(&g_n_needed, 1);
        g_needed_nodes[s] = node;
        g_slot[node] = s + 2;
    }
}

// ---------------- 2) edge scan: 4 edges/thread, vectorized dst -------------
__global__ void __launch_bounds__(256)
k_scan(const void* __restrict__ edge_index,
       const void* __restrict__ edge_type,
       const float* __restrict__ x,
       int n_edge, int n_rel) {
    int is64 = g_is64;
    int e0 = (blockIdx.x * blockDim.x + threadIdx.x) * 4;
    if (e0 >= n_edge) return;

    int dst[4];
    int nv = (e0 + 4 <= n_edge) ? 4 : (n_edge - e0);
    if (nv == 4) {
        if (!is64) {
            int4 v = *(const int4*)((const int*)edge_index + (size_t)n_edge + e0);
            dst[0] = v.x; dst[1] = v.y; dst[2] = v.z; dst[3] = v.w;
        } else {
            longlong2 a = *(const longlong2*)((const long long*)edge_index + (size_t)n_edge + e0);
            longlong2 b = *(const longlong2*)((const long long*)edge_index + (size_t)n_edge + e0 + 2);
            dst[0] = (int)a.x; dst[1] = (int)a.y; dst[2] = (int)b.x; dst[3] = (int)b.y;
        }
    } else {
        for (int k = 0; k < nv; k++) dst[k] = ld_idx(edge_index, (size_t)n_edge + e0 + k, is64);
    }

#pragma unroll
    for (int k = 0; k < 4; k++) {
        if (k >= nv) break;
        int s = g_slot[dst[k]] - 2;
        if (s < 0) continue;
        int e   = e0 + k;
        int r   = ld_idx(edge_type, e, is64);
        int src = ld_idx(edge_index, e, is64);
        atomicAdd(&g_cnt[s * n_rel + r], 1.0f);
        const float4* xs = (const float4*)(x + (size_t)src * DIM);
        float* m = &g_msg[((size_t)s * n_rel + r) * DIM];
#pragma unroll
        for (int j = 0; j < DIM / 4; j++) {
            float4 v = xs[j];
            atomicAdd(&m[4 * j + 0], v.x);
            atomicAdd(&m[4 * j + 1], v.y);
            atomicAdd(&m[4 * j + 2], v.z);
            atomicAdd(&m[4 * j + 3], v.w);
        }
    }
}

// ---------------- 3) per-(rel, half, slot-group) GEMM -----------------------
// grid = (n_rel + 1) * 2 * GROUPS blocks of 128 threads.
// r < n_rel: msg_mean[slot][r] @ W_rel[r];  r == n_rel: x[node] @ W_root.
__global__ void __launch_bounds__(128)
k_gemm(const float* __restrict__ W_rel,
       const float* __restrict__ W_root,
       const float* __restrict__ x,
       int n_rel) {
    __shared__ float Ws[64 * DIM];   // Ws[d * 64 + c]  (one 64-col half)
    __shared__ float ms[DIM];

    int idx  = blockIdx.x;
    int r    = idx % (n_rel + 1);
    int half = (idx / (n_rel + 1)) & 1;
    int sg   = idx / ((n_rel + 1) * 2);
    const float* W = (r < n_rel) ? (W_rel + (size_t)r * DIM * DIM) : W_root;
    int tid = threadIdx.x;
    int nn = g_n_needed;
    if (idx == 0 && tid == 0) g_nn_copy = nn;   // snapshot for cleanup

    int fbase = half * 64;
    for (int i = tid; i < 64 * DIM; i += 128) {
        int d = i >> 6, c = i & 63;
        Ws[i] = W[d * DIM + fbase + c];
    }
    __syncthreads();

    int c  = tid & 63;
    int dh = (tid >> 6) * 64;

    for (int s = sg; s < nn; s += GROUPS) {
        bool skip = false;
        float scale = 1.0f;
        if (r < n_rel) {
            float cnt = g_cnt[s * n_rel + r];   // uniform across block
            if (cnt == 0.0f) skip = true;
            else scale = 1.0f / cnt;
        }
        if (!skip) {
            if (r < n_rel)
                ms[tid] = g_msg[((size_t)s * n_rel + r) * DIM + tid] * scale;
            else
                ms[tid] = x[(size_t)g_needed_nodes[s] * DIM + tid];
        }
        __syncthreads();
        if (!skip) {
            float acc = 0.0f;
#pragma unroll
            for (int k = 0; k < 16; k++) {
                int d = dh + k * 4;
                float4 mv = *(const float4*)&ms[d];
                acc += mv.x * Ws[(d + 0) * 64 + c];
                acc += mv.y * Ws[(d + 1) * 64 + c];
                acc += mv.z * Ws[(d + 2) * 64 + c];
                acc += mv.w * Ws[(d + 3) * 64 + c];
            }
            atomicAdd(&g_agg[s * DIM + fbase + c], acc);
        }
        __syncthreads();
    }
}

// ---------------- 4) fused gather + fast-tanh epilogue + msg/cnt clean -----
__global__ void __launch_bounds__(256)
k_out(const void* __restrict__ sample,
      const float* __restrict__ init_rel,
      float* __restrict__ out,
      int batch, int n_rel) {
    // absorb g_msg / g_cnt zeroing (gemm is done; out doesn't read them)
    {
        int nn = g_nn_copy;
        int tid = blockIdx.x * blockDim.x + threadIdx.x;
        int stride = gridDim.x * blockDim.x;
        int n_msg = nn * n_rel * DIM;
        for (int i = tid; i < n_msg; i += stride) g_msg[i] = 0.0f;
        int n_cnt = nn * n_rel;
        for (int i = tid; i < n_cnt; i += stride) g_cnt[i] = 0.0f;
    }

    int is64 = g_is64;
    int i = blockIdx.x * blockDim.x + threadIdx.x;
    if (i >= batch * DIM) return;
    int b = i >> 7;
    int d = i & (DIM - 1);
    int h   = ld_idx(sample, (size_t)b * 3 + 0, is64);
    int rel = ld_idx(sample, (size_t)b * 3 + 1, is64);
    int t   = ld_idx(sample, (size_t)b * 3 + 2, is64);
    int sh = g_slot[h] - 2;
    int st = g_slot[t] - 2;
    float hv = ftanh(g_agg[sh * DIM + d]);
    float tv = ftanh(g_agg[st * DIM + d]);
    out[i] = hv * (init_rel[rel * DIM + d] * tv);
}

// ---------------- 5) tiny self-clean: agg + slot + counters ----------------
__global__ void k_cleanup() {
    int nn = g_nn_copy;
    int tid = blockIdx.x * blockDim.x + threadIdx.x;
    int stride = gridDim.x * blockDim.x;
    for (int i = tid; i < nn * DIM; i += stride) g_agg[i] = 0.0f;
    for (int i = tid; i < nn; i += stride) g_slot[g_needed_nodes[i]] = 0;
    if (tid == 0) g_n_needed = 0;
}

// ---------------- launch ----------------
extern "C" void kernel_launch(void* const* d_in, const int* in_sizes, int n_in,
                              void* d_out, int out_size) {
    const float* init_embed = (const float*)d_in[0];
    const float* init_rel   = (const float*)d_in[1];
    const float* W_rel      = (const float*)d_in[2];
    const float* W_root     = (const float*)d_in[3];
    const void*  edge_index = d_in[4];
    const void*  edge_type  = d_in[5];
    const void*  sample     = d_in[6];
    float* out = (float*)d_out;

    int n_rel  = in_sizes[1] / DIM;
    int n_edge = in_sizes[5];
    int batch  = in_sizes[6] / 3;

    k_mark   <<<(batch * 2 + 255) / 256, 256>>>((const unsigned int*)edge_index,
                                                sample, batch);
    k_scan   <<<(n_edge + 4 * 256 - 1) / (4 * 256), 256>>>(edge_index, edge_type,
                                                           init_embed, n_edge, n_rel);
    k_gemm   <<<(n_rel + 1) * 2 * GROUPS, 128>>>(W_rel, W_root, init_embed, n_rel);
    k_out    <<<(batch * DIM + 255) / 256, 256>>>(sample, init_rel, out, batch, n_rel);
    k_cleanup<<<16, 256>>>();
}